// round 12
// baseline (speedup 1.0000x reference)
#include <cuda_runtime.h>
#include <cuda_bf16.h>

// MX quantize-dequantize: block size 32, E8M0 shared scale, E4M3 elements.
// v8: persistent single-wave kernel. grid = 148*8 = 1184 CTAs (one wave at
// occ 8), each warp grid-strides over 64-float4 windows (~14 iters/warp),
// eliminating the ~13 wave transitions the 16384-CTA launch pays. Inside an
// iteration: R8's proven layout — two contiguous-512B LDG.128 per warp
// window (lane l: base+l and base+32+l), dual interleaved 8-lane shfl amax
// reductions. Exact pow2 bit-constructed scale math.

__device__ __forceinline__ float mx_qdq_elem(float v, float inv_scale, float scale) {
    unsigned sbit = __float_as_uint(v) & 0x80000000u;
    float mag = fabsf(v) * inv_scale;          // exact pow2 multiply
    mag = fminf(mag, 448.0f);                  // E4M3 saturate
    float safe = fmaxf(mag, 0.015625f);        // 2^-6 (subnormal region -> emin)
    int e = (int)(__float_as_uint(safe) >> 23) - 127;
    float quantum = __uint_as_float((unsigned)((e - 3) + 127) << 23); // 2^(e-3)
    float invq    = __uint_as_float((unsigned)((3 - e) + 127) << 23); // 2^(3-e)
    float q = rintf(mag * invq) * quantum * scale; // round-half-even, dequant
    return __uint_as_float(__float_as_uint(q) | sbit);
}

__device__ __forceinline__ float amax4(const float4& a) {
    return fmaxf(fmaxf(fabsf(a.x), fabsf(a.y)), fmaxf(fabsf(a.z), fabsf(a.w)));
}

__device__ __forceinline__ void scales_from_amax(float m, float& scale, float& inv_scale) {
    // shared_exp = floor(log2(amax)) - 8, exact via exponent-field extract;
    // clamp keeps the bit-constructed pow2 floats normal. amax==0 -> all
    // elements are zero -> scale value irrelevant.
    int se = ((int)(__float_as_uint(m) >> 23) - 127) - 8;
    se = max(se, -126);
    scale     = __uint_as_float((unsigned)(se + 127) << 23);
    inv_scale = __uint_as_float((unsigned)(127 - se) << 23);
}

__device__ __forceinline__ float4 qdq4(const float4& a, float inv_scale, float scale) {
    float4 o;
    o.x = mx_qdq_elem(a.x, inv_scale, scale);
    o.y = mx_qdq_elem(a.y, inv_scale, scale);
    o.z = mx_qdq_elem(a.z, inv_scale, scale);
    o.w = mx_qdq_elem(a.w, inv_scale, scale);
    return o;
}

__global__ void __launch_bounds__(256, 8)
mx_qdq_kernel(const float4* __restrict__ x, float4* __restrict__ y,
              int n_windows, int n_warps) {
    int lane  = threadIdx.x & 31;
    int warp0 = (blockIdx.x * blockDim.x + threadIdx.x) >> 5; // global warp id

    for (int win = warp0; win < n_windows; win += n_warps) {
        int base = win * 64;           // warp window: 64 consecutive float4 (1KB)
        int i0 = base + lane;          // load A: contiguous 512B across the warp
        int i1 = i0 + 32;              // load B: next contiguous 512B

        float4 a = x[i0];
        float4 b = x[i1];

        float mA = amax4(a);
        float mB = amax4(b);

        // Two independent 8-lane reductions (lanes 8k..8k+7 share one MX
        // block per load); interleaved so SHFL latency overlaps.
        float tA = __shfl_xor_sync(0xffffffffu, mA, 1);
        float tB = __shfl_xor_sync(0xffffffffu, mB, 1);
        mA = fmaxf(mA, tA);
        mB = fmaxf(mB, tB);
        tA = __shfl_xor_sync(0xffffffffu, mA, 2);
        tB = __shfl_xor_sync(0xffffffffu, mB, 2);
        mA = fmaxf(mA, tA);
        mB = fmaxf(mB, tB);
        tA = __shfl_xor_sync(0xffffffffu, mA, 4);
        tB = __shfl_xor_sync(0xffffffffu, mB, 4);
        mA = fmaxf(mA, tA);
        mB = fmaxf(mB, tB);

        float sA, isA, sB, isB;
        scales_from_amax(mA, sA, isA);
        scales_from_amax(mB, sB, isB);

        y[i0] = qdq4(a, isA, sA);
        y[i1] = qdq4(b, isB, sB);
    }
}

extern "C" void kernel_launch(void* const* d_in, const int* in_sizes, int n_in,
                              void* d_out, int out_size) {
    const float* x = (const float*)d_in[0];
    float*       y = (float*)d_out;
    int n    = in_sizes[0];            // 33,554,432 (divisible by 32)
    int nvec = n / 4;                  // 8,388,608 float4
    int n_windows = nvec / 64;         // 131,072 warp windows (1KB each)
    int block = 256;
    int grid  = 148 * 8;               // 1184 CTAs: exactly one wave at occ 8
    int n_warps = grid * (block / 32); // 9472 warps
    mx_qdq_kernel<<<grid, block>>>((const float4*)x, (float4*)y, n_windows, n_warps);
}

// round 14
// speedup vs baseline: 1.1017x; 1.1017x over previous
#include <cuda_runtime.h>
#include <cuda_bf16.h>
#include <cuda_fp16.h>

// MX quantize-dequantize: block size 32, E8M0 shared scale, E4M3 elements.
// v9b: R8's winning layout (interleaved lane mapping, 2x contiguous-512B
// LDG.128 per warp per load, dual interleaved 8-lane shfl reductions,
// grid 16384 x 256) with the element quantizer on NATIVE E4M3 conversion
// hardware: cvt.rn.satfinite.e4m3x2.f32 (b16 dest!) implements exactly the
// reference's round-half-even + saturate-448 + shared-emin-subnormal
// semantics; cvt.rn.f16x2.e4m3x2 converts back exactly (E4M3 subset of
// f16). Scale stays exact pow2 bit math.

__device__ __forceinline__ void scales_from_amax(float m, float& scale, float& inv_scale) {
    // shared_exp = floor(log2(amax)) - 8, exact via exponent-field extract;
    // clamp keeps the bit-constructed pow2 floats normal. amax==0 -> all
    // elements are zero -> scale value irrelevant.
    int se = ((int)(__float_as_uint(m) >> 23) - 127) - 8;
    se = max(se, -126);
    scale     = __uint_as_float((unsigned)(se + 127) << 23);
    inv_scale = __uint_as_float((unsigned)(127 - se) << 23);
}

__device__ __forceinline__ float amax4(const float4& a) {
    return fmaxf(fmaxf(fabsf(a.x), fabsf(a.y)), fmaxf(fabsf(a.z), fabsf(a.w)));
}

// Quantize-dequantize two elements via the HW E4M3 converter.
// lo/hi already divided by scale; returns dequantized (x scale) pair.
__device__ __forceinline__ float2 qdq2_hw(float lo, float hi, float scale) {
    unsigned short e4m3x2;
    // d[7:0] = cvt(b=lo), d[15:8] = cvt(a=hi): RN-even, satfinite at 448.
    asm("cvt.rn.satfinite.e4m3x2.f32 %0, %1, %2;"
        : "=h"(e4m3x2) : "f"(hi), "f"(lo));
    unsigned h2bits;
    // exact: every e4m3 value is representable in f16
    asm("cvt.rn.f16x2.e4m3x2 %0, %1;" : "=r"(h2bits) : "h"(e4m3x2));
    __half2 h2 = *reinterpret_cast<__half2*>(&h2bits);
    float2 f = __half22float2(h2);   // f.x = lo, f.y = hi
    f.x *= scale;                    // exact pow2 multiply
    f.y *= scale;
    return f;
}

__device__ __forceinline__ float4 qdq4(const float4& a, float inv_scale, float scale) {
    float2 p0 = qdq2_hw(a.x * inv_scale, a.y * inv_scale, scale);
    float2 p1 = qdq2_hw(a.z * inv_scale, a.w * inv_scale, scale);
    float4 o;
    o.x = p0.x; o.y = p0.y; o.z = p1.x; o.w = p1.y;
    return o;
}

__global__ void __launch_bounds__(256)
mx_qdq_kernel(const float4* __restrict__ x, float4* __restrict__ y, int nvec) {
    int t    = blockIdx.x * blockDim.x + threadIdx.x;
    int lane = t & 31;
    int warp = t >> 5;
    int base = warp * 64;          // warp window: 64 consecutive float4 (1KB)
    int i0 = base + lane;          // load A: contiguous 512B across the warp
    int i1 = base + 32 + lane;     // load B: next contiguous 512B

    if (i1 >= nvec) {
        if (i0 < nvec) {
            float4 a = x[i0];
            float m = amax4(a);
            m = fmaxf(m, __shfl_xor_sync(0xffffffffu, m, 1));
            m = fmaxf(m, __shfl_xor_sync(0xffffffffu, m, 2));
            m = fmaxf(m, __shfl_xor_sync(0xffffffffu, m, 4));
            float s, is; scales_from_amax(m, s, is);
            y[i0] = qdq4(a, is, s);
        }
        return;
    }

    float4 a = x[i0];
    float4 b = x[i1];

    float mA = amax4(a);
    float mB = amax4(b);

    // Two independent 8-lane reductions (lanes 8k..8k+7 share one MX block
    // per load); interleaved so SHFL latency overlaps.
    float tA = __shfl_xor_sync(0xffffffffu, mA, 1);
    float tB = __shfl_xor_sync(0xffffffffu, mB, 1);
    mA = fmaxf(mA, tA);
    mB = fmaxf(mB, tB);
    tA = __shfl_xor_sync(0xffffffffu, mA, 2);
    tB = __shfl_xor_sync(0xffffffffu, mB, 2);
    mA = fmaxf(mA, tA);
    mB = fmaxf(mB, tB);
    tA = __shfl_xor_sync(0xffffffffu, mA, 4);
    tB = __shfl_xor_sync(0xffffffffu, mB, 4);
    mA = fmaxf(mA, tA);
    mB = fmaxf(mB, tB);

    float sA, isA, sB, isB;
    scales_from_amax(mA, sA, isA);
    scales_from_amax(mB, sB, isB);

    y[i0] = qdq4(a, isA, sA);
    y[i1] = qdq4(b, isB, sB);
}

extern "C" void kernel_launch(void* const* d_in, const int* in_sizes, int n_in,
                              void* d_out, int out_size) {
    const float* x = (const float*)d_in[0];
    float*       y = (float*)d_out;
    int n    = in_sizes[0];        // 33,554,432 (divisible by 32)
    int nvec = n / 4;              // 8,388,608 float4
    int nthreads = nvec / 2;       // 8 elements per thread
    int block = 256;
    int grid  = (nthreads + block - 1) / block;  // 16384
    mx_qdq_kernel<<<grid, block>>>((const float4*)x, (float4*)y, nvec);
}